// round 17
// baseline (speedup 1.0000x reference)
#include <cuda_runtime.h>
#include <math.h>

typedef unsigned long long ull;

#define BB   32
#define SSN  400
#define HHN  256
#define H2N  512
#define EEN  300
#define VVN  50000
#define VXN  50050
#define VXPN 50052
#define TTN  20
#define G4N  1024

// -------- device scratch --------
__device__ float g_enc_feat[(size_t)BB*SSN*HHN];
__device__ float g_planes[(size_t)TTN*BB*VXPN];
__device__ float g_embAll[(size_t)TTN*BB*EEN];
__device__ float g_hb[2][BB*HHN];            // parity double buffer
__device__ float g_c[BB*HHN];
__device__ float g_gates[BB*G4N];
__device__ float g_dec[BB*HHN];
__device__ float g_cov[BB*SSN];
__device__ float g_p[BB*SSN];
__device__ float g_ctxb[2][BB*H2N];          // parity double buffer
__device__ float g_out1v[2*BB*HHN];          // parity double buffer
__device__ float g_esum[TTN*BB];
__device__ float g_S[TTN*BB];
__device__ float g_pgacc[TTN*BB];

// -------- helpers --------
__device__ __forceinline__ ull pack2(float x, float y){
    ull r; asm("mov.b64 %0, {%1, %2};" : "=l"(r) : "r"(__float_as_uint(x)), "r"(__float_as_uint(y)));
    return r;
}
__device__ __forceinline__ void ffma2(ull &d, ull a, ull b){
    asm("fma.rn.f32x2 %0, %1, %2, %0;" : "+l"(d) : "l"(a), "l"(b));
}
__device__ __forceinline__ float2 unpack2(ull v){
    unsigned lo, hi; asm("mov.b64 {%0, %1}, %2;" : "=r"(lo), "=r"(hi) : "l"(v));
    return make_float2(__uint_as_float(lo), __uint_as_float(hi));
}
__device__ __forceinline__ float sigm(float x){ return 1.f/(1.f+expf(-x)); }
__device__ __forceinline__ float2 tanh2_a(float x, float y){
    unsigned p, r;
    asm("cvt.rn.f16x2.f32 %0, %1, %2;" : "=r"(p) : "f"(x), "f"(y));
    asm("tanh.approx.f16x2 %0, %1;" : "=r"(r) : "r"(p));
    float fx, fy;
    asm("{ .reg .b16 lo, hi; mov.b32 {lo, hi}, %2; cvt.f32.f16 %0, hi; cvt.f32.f16 %1, lo; }"
        : "=f"(fx), "=f"(fy) : "r"(r));
    return make_float2(fx, fy);
}

// -------- init --------
__global__ void k_init(const float* __restrict__ h0, const float* __restrict__ c0){
    int i = blockIdx.x*blockDim.x + threadIdx.x;
    int n = blockDim.x*gridDim.x;
    for(int j=i;j<BB*HHN;j+=n){ g_hb[1][j]=h0[j]; g_c[j]=c0[j]; }
    for(int j=i;j<BB*SSN;j+=n) g_cov[j]=0.f;
    for(int j=i;j<BB*G4N;j+=n) g_gates[j]=0.f;
    for(int j=i;j<TTN*BB;j+=n){ g_esum[j]=0.f; g_S[j]=0.f; g_pgacc[j]=0.f; }
}

// -------- gather all decoder-input embeddings once --------
__global__ void k_emball(const float* __restrict__ emb_tab,
                         const int* __restrict__ dec_input){
    int b = blockIdx.x, t = blockIdx.y, tid = threadIdx.x;
    int x = dec_input[b*TTN + t];
    if(tid < EEN)
        g_embAll[((size_t)t*BB+b)*EEN + tid] = emb_tab[(size_t)x*EEN + tid];
}

// -------- enc_feat = enc_hidden @ W_enc : [12800,512]x[512,256] --------
__global__ __launch_bounds__(256) void k_encfeat(const float* __restrict__ eh,
                                                 const float* __restrict__ Wenc){
    __shared__ float As[64][66];
    int tid = threadIdx.x;
    int cg  = tid & 63;
    int rt  = tid >> 6;
    int row0 = blockIdx.x * 64;
    ull acc[4][8];
    #pragma unroll
    for(int c=0;c<4;c++)
        #pragma unroll
        for(int p=0;p<8;p++) acc[c][p]=0ull;

    for(int kc=0; kc<512; kc+=64){
        __syncthreads();
        for(int i=tid;i<64*64;i+=256){
            int r=i>>6, k=i&63;
            As[k][r] = eh[(size_t)(row0+r)*512 + kc + k];
        }
        __syncthreads();
        #pragma unroll 4
        for(int k=0;k<64;k++){
            float4 w4 = *(const float4*)&Wenc[(size_t)(kc+k)*HHN + cg*4];
            ull wp0=pack2(w4.x,w4.x), wp1=pack2(w4.y,w4.y);
            ull wp2=pack2(w4.z,w4.z), wp3=pack2(w4.w,w4.w);
            #pragma unroll
            for(int p=0;p<8;p++){
                ull a = *(const ull*)&As[k][rt*16 + 2*p];
                ffma2(acc[0][p], wp0, a);
                ffma2(acc[1][p], wp1, a);
                ffma2(acc[2][p], wp2, a);
                ffma2(acc[3][p], wp3, a);
            }
        }
    }
    #pragma unroll
    for(int p=0;p<8;p++){
        float2 u0=unpack2(acc[0][p]), u1=unpack2(acc[1][p]);
        float2 u2=unpack2(acc[2][p]), u3=unpack2(acc[3][p]);
        int r0 = row0 + rt*16 + 2*p;
        *(float4*)&g_enc_feat[(size_t)r0*HHN + cg*4]     = make_float4(u0.x,u1.x,u2.x,u3.x);
        *(float4*)&g_enc_feat[(size_t)(r0+1)*HHN + cg*4] = make_float4(u0.y,u1.y,u2.y,u3.y);
    }
}

// -------- split-K skinny GEMM core, MLP=16 weight prefetch --------
__device__ __forceinline__ void skinny_core(const float* __restrict__ W, int N,
        const float* __restrict__ Xb, int xstr, int xoff, int wk0, int kl,
        float* __restrict__ Y, float (*Xs)[32]){
    int tid = threadIdx.x, lane = tid & 31, bq = tid >> 5;
    int col = blockIdx.x*32 + lane;
    for(int i2=tid; i2<kl*32; i2+=256){
        int k=i2>>5, b=i2&31;
        Xs[k][b] = Xb[(size_t)b*xstr + xoff + k];
    }
    __syncthreads();
    float a0=0.f,a1=0.f,a2=0.f,a3=0.f;
    const float* Wp = W + (size_t)wk0*N + col;
    int kk=0;
    for(; kk+16<=kl; kk+=16){
        float w[16];
        #pragma unroll
        for(int i=0;i<16;i++) w[i]=Wp[(size_t)(kk+i)*N];
        #pragma unroll
        for(int i=0;i<16;i++){
            float4 x=*(const float4*)&Xs[kk+i][4*bq];
            a0+=x.x*w[i]; a1+=x.y*w[i]; a2+=x.z*w[i]; a3+=x.w*w[i];
        }
    }
    for(; kk<kl; kk++){
        float w=Wp[(size_t)kk*N];
        float4 x=*(const float4*)&Xs[kk][4*bq];
        a0+=x.x*w; a1+=x.y*w; a2+=x.z*w; a3+=x.w*w;
    }
    int b0=4*bq;
    atomicAdd(&Y[(size_t)(b0+0)*N+col],a0);
    atomicAdd(&Y[(size_t)(b0+1)*N+col],a1);
    atomicAdd(&Y[(size_t)(b0+2)*N+col],a2);
    atomicAdd(&Y[(size_t)(b0+3)*N+col],a3);
}

// gates for step t: reads h[(t-1)&1]; ch 0-4 = W_ih, ch 5-8 = W_hh
__global__ __launch_bounds__(256) void k_gates2(const float* __restrict__ Wih,
                                                const float* __restrict__ Whh, int t){
    __shared__ float Xs[64][32];
    int ch = blockIdx.y;
    if(ch < 5){
        int k0 = ch*64, kl = (ch==4)?44:64;
        skinny_core(Wih, G4N, g_embAll + (size_t)t*BB*EEN, EEN, k0, k0, kl, g_gates, Xs);
    } else {
        int k0 = (ch-5)*64;
        skinny_core(Whh, G4N, g_hb[(t+1)&1], HHN, k0, k0, 64, g_gates, Xs);
    }
}

// LSTM elementwise (+bias) + zero gates/out1v[p] + dec = h @ W_dec; h -> g_hb[p]
__global__ __launch_bounds__(256) void k_lstmdec(const float* __restrict__ Wdec,
                                                 const float* __restrict__ blstm, int p){
    __shared__ float hs[256];
    int b = blockIdx.x, j = threadIdx.x;
    int gbase = b*G4N;
    float gi = g_gates[gbase+j]     + blstm[j];
    float gf = g_gates[gbase+256+j] + blstm[256+j];
    float gg = g_gates[gbase+512+j] + blstm[512+j];
    float go = g_gates[gbase+768+j] + blstm[768+j];
    float c = sigm(gf)*g_c[b*HHN+j] + sigm(gi)*tanhf(gg);
    g_c[b*HHN+j] = c;
    float h = sigm(go)*tanhf(c);
    g_hb[p][b*HHN+j] = h;
    hs[j] = h;
    g_gates[gbase+j]=0.f; g_gates[gbase+256+j]=0.f;
    g_gates[gbase+512+j]=0.f; g_gates[gbase+768+j]=0.f;
    g_out1v[(size_t)p*BB*HHN + b*HHN + j]=0.f;
    __syncthreads();
    float a=0.f;
    for(int kk=0;kk<256;kk+=16){
        float w[16];
        #pragma unroll
        for(int i=0;i<16;i++) w[i]=Wdec[(size_t)(kk+i)*HHN + j];
        #pragma unroll
        for(int i=0;i<16;i++) a += hs[kk+i]*w[i];
    }
    g_dec[b*HHN+j] = a;
}

// -------- attention scores -> exp + sums; ch==0 zeroes ctx[p] --------
__global__ __launch_bounds__(256) void k_escore(const float* __restrict__ wcov,
                                                const float* __restrict__ vattn,
                                                int p, int t){
    __shared__ float df[256], wc[256], va[256];
    int b = blockIdx.y, tid = threadIdx.x;
    if(blockIdx.x == 0){
        g_ctxb[p][b*H2N+tid] = 0.f;
        g_ctxb[p][b*H2N+256+tid] = 0.f;
    }
    df[tid]=g_dec[b*HHN+tid]; wc[tid]=wcov[tid]; va[tid]=vattn[tid];
    __syncthreads();
    int w = tid>>5, lane = tid&31;
    int h0 = lane*8;
    float wsum = 0.f;
    for(int si=0; si<10; si++){
        int s = blockIdx.x*80 + w*10 + si;
        float cs = g_cov[b*SSN+s];
        const float* ef = &g_enc_feat[((size_t)b*SSN+s)*HHN + h0];
        float4 e0 = *(const float4*)ef;
        float4 e1 = *(const float4*)(ef+4);
        float a0 = e0.x + df[h0+0] + cs*wc[h0+0];
        float a1 = e0.y + df[h0+1] + cs*wc[h0+1];
        float a2 = e0.z + df[h0+2] + cs*wc[h0+2];
        float a3 = e0.w + df[h0+3] + cs*wc[h0+3];
        float a4 = e1.x + df[h0+4] + cs*wc[h0+4];
        float a5 = e1.y + df[h0+5] + cs*wc[h0+5];
        float a6 = e1.z + df[h0+6] + cs*wc[h0+6];
        float a7 = e1.w + df[h0+7] + cs*wc[h0+7];
        float2 t01 = tanh2_a(a0,a1);
        float2 t23 = tanh2_a(a2,a3);
        float2 t45 = tanh2_a(a4,a5);
        float2 t67 = tanh2_a(a6,a7);
        float sum = t01.x*va[h0+0] + t01.y*va[h0+1]
                  + t23.x*va[h0+2] + t23.y*va[h0+3]
                  + t45.x*va[h0+4] + t45.y*va[h0+5]
                  + t67.x*va[h0+6] + t67.y*va[h0+7];
        #pragma unroll
        for(int o=16;o>0;o>>=1) sum += __shfl_down_sync(0xffffffffu, sum, o);
        if(lane==0){ float pp = expf(sum); g_p[b*SSN+s]=pp; wsum += pp; }
    }
    if(lane==0) atomicAdd(&g_esum[t*BB+b], wsum);
}

// -------- normalize attn, cov update, outputs, context, p_gen partial --------
__global__ __launch_bounds__(512) void k_attnctx(const float* __restrict__ eh,
        const float* __restrict__ wh, const float* __restrict__ ws,
        const float* __restrict__ wx, const float* __restrict__ bx,
        float* __restrict__ outA, float* __restrict__ outC, int p, int t){
    __shared__ float at[100];
    __shared__ float red[512];
    int b = blockIdx.y, ch = blockIdx.x, tid = threadIdx.x;
    float inv = 1.f/g_esum[t*BB+b];
    if(tid < 100){
        int s = ch*100 + tid;
        float a = g_p[b*SSN+s]*inv;
        at[tid]=a;
        float cv = g_cov[b*SSN+s]+a;
        g_cov[b*SSN+s]=cv;
        outA[((size_t)b*SSN+s)*TTN + t]=a;
        outC[((size_t)b*SSN+s)*TTN + t]=cv;
    }
    __syncthreads();
    float acc=0.f;
    const float* ep = &eh[((size_t)(b*SSN + ch*100))*H2N + tid];
    #pragma unroll 10
    for(int i=0;i<100;i++) acc += at[i]*ep[(size_t)i*H2N];
    atomicAdd(&g_ctxb[p][b*H2N+tid], acc);
    float part = acc*wh[tid];
    if(ch == 0){
        if(tid<256) part += g_hb[p][b*HHN+tid]*ws[tid];
        if(tid<300) part += g_embAll[((size_t)t*BB+b)*EEN+tid]*wx[tid];
        if(tid==0)  part += bx[0];
    }
    red[tid]=part;
    __syncthreads();
    for(int st=256; st>0; st>>=1){
        if(tid<st) red[tid]+=red[tid+st];
        __syncthreads();
    }
    if(tid==0) atomicAdd(&g_pgacc[t*BB+b], red[0]);
}

// out1 += [h|ctx] @ W_out1 : grid (8, 12)
__global__ __launch_bounds__(256) void k_out1s(const float* __restrict__ W1, int p){
    __shared__ float Xs[64][32];
    float* Y = g_out1v + (size_t)p*BB*HHN;
    int ch = blockIdx.y;
    if(ch < 4){
        int k0 = ch*64;
        skinny_core(W1, HHN, g_hb[p], HHN, k0, k0, 64, Y, Xs);
    } else {
        int k0 = (ch-4)*64;
        skinny_core(W1, HHN, g_ctxb[p], H2N, k0, 256+k0, 64, Y, Xs);
    }
}

// -------- logits GEMM [32,256]x[256,50000] -> exp plane + sums --------
__global__ __launch_bounds__(128) void k_bigmm(const float* __restrict__ W2,
                                               const float* __restrict__ b1,
                                               const float* __restrict__ b2,
                                               int p, int t){
    __shared__ float As[256][32];
    const float* X = g_out1v + (size_t)p*BB*HHN;
    int tid = threadIdx.x;
    int cg = tid & 31, bg = tid >> 5;
    int col0 = blockIdx.x*128 + cg*4;
    bool vld = col0 < VVN;
    for(int i=tid;i<8192;i+=128){
        int k=i>>5,b=i&31;
        As[k][b]=X[b*HHN+k] + b1[k];
    }
    __syncthreads();
    ull acc[4][4];
    #pragma unroll
    for(int c=0;c<4;c++)
        #pragma unroll
        for(int q=0;q<4;q++) acc[c][q]=0ull;

    for(int kk=0;kk<256;kk+=8){
        float4 w[8];
        #pragma unroll
        for(int i=0;i<8;i++)
            w[i] = vld ? *(const float4*)&W2[(size_t)(kk+i)*VVN + col0]
                       : make_float4(0.f,0.f,0.f,0.f);
        #pragma unroll
        for(int i=0;i<8;i++){
            ull wp0=pack2(w[i].x,w[i].x), wp1=pack2(w[i].y,w[i].y);
            ull wp2=pack2(w[i].z,w[i].z), wp3=pack2(w[i].w,w[i].w);
            ulonglong2 a01 = *(const ulonglong2*)&As[kk+i][bg*8];
            ulonglong2 a23 = *(const ulonglong2*)&As[kk+i][bg*8+4];
            ffma2(acc[0][0],wp0,a01.x); ffma2(acc[0][1],wp0,a01.y);
            ffma2(acc[0][2],wp0,a23.x); ffma2(acc[0][3],wp0,a23.y);
            ffma2(acc[1][0],wp1,a01.x); ffma2(acc[1][1],wp1,a01.y);
            ffma2(acc[1][2],wp1,a23.x); ffma2(acc[1][3],wp1,a23.y);
            ffma2(acc[2][0],wp2,a01.x); ffma2(acc[2][1],wp2,a01.y);
            ffma2(acc[2][2],wp2,a23.x); ffma2(acc[2][3],wp2,a23.y);
            ffma2(acc[3][0],wp3,a01.x); ffma2(acc[3][1],wp3,a01.y);
            ffma2(acc[3][2],wp3,a23.x); ffma2(acc[3][3],wp3,a23.y);
        }
    }
    float psum[8];
    #pragma unroll
    for(int j=0;j<8;j++) psum[j]=0.f;
    if(vld){
        float4 bi = *(const float4*)&b2[col0];
        #pragma unroll
        for(int q=0;q<4;q++){
            float2 u0=unpack2(acc[0][q]), u1=unpack2(acc[1][q]);
            float2 u2=unpack2(acc[2][q]), u3=unpack2(acc[3][q]);
            float4 vlo = make_float4(expf(u0.x+bi.x), expf(u1.x+bi.y),
                                     expf(u2.x+bi.z), expf(u3.x+bi.w));
            float4 vhi = make_float4(expf(u0.y+bi.x), expf(u1.y+bi.y),
                                     expf(u2.y+bi.z), expf(u3.y+bi.w));
            int j0 = bg*8 + 2*q;
            *(float4*)&g_planes[(size_t)(t*BB + j0)*VXPN + col0]   = vlo;
            *(float4*)&g_planes[(size_t)(t*BB + j0+1)*VXPN + col0] = vhi;
            psum[2*q]   = vlo.x+vlo.y+vlo.z+vlo.w;
            psum[2*q+1] = vhi.x+vhi.y+vhi.z+vhi.w;
        }
    }
    #pragma unroll
    for(int j=0;j<8;j++){
        float s = psum[j];
        #pragma unroll
        for(int o=16;o>0;o>>=1) s += __shfl_down_sync(0xffffffffu, s, o);
        if((tid&31)==0 && s!=0.f) atomicAdd(&g_S[t*BB + bg*8 + j], s);
    }
}

// -------- finalize --------
__global__ __launch_bounds__(256) void k_finalize(float* __restrict__ outF){
    __shared__ float sc[20];
    int b = blockIdx.y, tid = threadIdx.x;
    if(tid < 20) sc[tid] = sigm(g_pgacc[tid*BB+b]) / g_S[tid*BB+b];
    __syncthreads();
    int v = blockIdx.x*256 + tid;
    if(v >= VXN) return;
    float vals[20];
    if(v < VVN){
        #pragma unroll
        for(int tt=0;tt<TTN;tt++)
            vals[tt] = sc[tt] * g_planes[(size_t)(tt*BB+b)*VXPN + v];
    } else {
        #pragma unroll
        for(int tt=0;tt<TTN;tt++) vals[tt]=0.f;
    }
    float4* o = (float4*)&outF[((size_t)b*VXN + v)*TTN];
    #pragma unroll
    for(int q=0;q<5;q++)
        o[q] = make_float4(vals[4*q],vals[4*q+1],vals[4*q+2],vals[4*q+3]);
}

// -------- scatter-add copy probabilities --------
__global__ __launch_bounds__(256) void k_scatter(const int* __restrict__ ext,
        float* __restrict__ outF, const float* __restrict__ outA){
    int gid = blockIdx.x*256 + threadIdx.x;
    if(gid >= BB*SSN) return;
    int b = gid / SSN, s = gid - b*SSN;
    int e = ext[b*SSN + s];
    float* dst = &outF[((size_t)b*VXN + e)*TTN];
    const float* ap = &outA[((size_t)b*SSN + s)*TTN];
    #pragma unroll
    for(int tt=0;tt<TTN;tt++)
        atomicAdd(&dst[tt], (1.f - sigm(g_pgacc[tt*BB+b])) * ap[tt]);
}

extern "C" void kernel_launch(void* const* d_in, const int* in_sizes, int n_in,
                              void* d_out, int out_size){
    const float* enc_hidden = (const float*)d_in[0];
    const float* h0        = (const float*)d_in[1];
    const float* c0        = (const float*)d_in[2];
    const float* embedding = (const float*)d_in[3];
    const float* W_enc     = (const float*)d_in[4];
    const float* W_dec     = (const float*)d_in[5];
    const float* w_cov     = (const float*)d_in[6];
    const float* v_attn    = (const float*)d_in[7];
    const float* W_ih      = (const float*)d_in[8];
    const float* W_hh      = (const float*)d_in[9];
    const float* b_lstm    = (const float*)d_in[10];
    const float* W_out1    = (const float*)d_in[11];
    const float* b_out1    = (const float*)d_in[12];
    const float* W_out2    = (const float*)d_in[13];
    const float* b_out2    = (const float*)d_in[14];
    const float* w_h       = (const float*)d_in[15];
    const float* w_s       = (const float*)d_in[16];
    const float* w_x       = (const float*)d_in[17];
    const float* b_x       = (const float*)d_in[18];
    const int*   dec_input = (const int*)d_in[19];
    const int*   enc_ext   = (const int*)d_in[20];
    float* outF = (float*)d_out;
    float* outA = outF + (size_t)BB*VXN*TTN;
    float* outC = outA + (size_t)BB*SSN*TTN;

    // ONE side stream (two total — three triggered a 2MB teardown violation in R15)
    static cudaStream_t s2 = 0;
    static cudaEvent_t evL[TTN], evA[TTN], evG[TTN], evEnd;
    if(!s2){
        cudaStreamCreateWithFlags(&s2, cudaStreamNonBlocking);
        for(int i=0;i<TTN;i++){
            cudaEventCreateWithFlags(&evL[i], cudaEventDisableTiming);
            cudaEventCreateWithFlags(&evA[i], cudaEventDisableTiming);
            cudaEventCreateWithFlags(&evG[i], cudaEventDisableTiming);
        }
        cudaEventCreateWithFlags(&evEnd, cudaEventDisableTiming);
    }

    k_init<<<256,256>>>(h0, c0);
    k_emball<<<dim3(BB,TTN),320>>>(embedding, dec_input);
    k_encfeat<<<200,256>>>(enc_hidden, W_enc);
    k_gates2<<<dim3(32,9),256>>>(W_ih, W_hh, 0);   // step-0 gates, in-stream
    for(int t=0;t<TTN;t++){
        int p = t & 1;
        // evG[t] (recorded on s2 after gates2(t)) transitively orders all older
        // s2 work (bigmm(t-1) etc.) -> out1v[p] reuse is safe without evB waits.
        if(t >= 1) cudaStreamWaitEvent(0, evG[t], 0);
        k_lstmdec<<<BB,256>>>(W_dec, b_lstm, p);
        cudaEventRecord(evL[t], 0);
        k_escore<<<dim3(5,BB),256>>>(w_cov, v_attn, p, t);
        k_attnctx<<<dim3(4,BB),512>>>(enc_hidden, w_h, w_s, w_x, b_x, outA, outC, p, t);
        cudaEventRecord(evA[t], 0);
        // s2: gates2(t+1) first (needs only lstmdec(t)), then out1s(t)+bigmm(t)
        if(t+1 < TTN){
            cudaStreamWaitEvent(s2, evL[t], 0);
            k_gates2<<<dim3(32,9),256,0,s2>>>(W_ih, W_hh, t+1);
            cudaEventRecord(evG[t+1], s2);
        }
        cudaStreamWaitEvent(s2, evA[t], 0);
        k_out1s<<<dim3(8,12),256,0,s2>>>(W_out1, p);
        k_bigmm<<<391,128,0,s2>>>(W_out2, b_out1, b_out2, p, t);
        if(t == TTN-1) cudaEventRecord(evEnd, s2);
    }
    cudaStreamWaitEvent(0, evEnd, 0);
    k_finalize<<<dim3(196,BB),256>>>(outF);
    k_scatter<<<(BB*SSN+255)/256,256>>>(enc_ext, outF, outA);
}